// round 11
// baseline (speedup 1.0000x reference)
#include <cuda_runtime.h>
#include <cuda_fp16.h>
#include <stdint.h>

#define B_   4
#define L_   2048
#define CIN  256
#define HID_ 1024
#define NH   8
#define HD   128
#define OUT_ 256
#define MTOT (B_*L_)   // 8192

// ---------------- scratch (device globals; no allocs allowed) ----------------
__device__ __align__(16) __half g_K16[(size_t)MTOT*CIN];
__device__ __align__(16) __half g_V16[(size_t)MTOT*CIN];
__device__ __align__(16) __half g_Q16[(size_t)MTOT*CIN];
__device__ __align__(16) __half g_Ww16[(size_t)HID_*CIN];   // PERMUTED rows: p=(n&7)*128+(n>>3)
__device__ __align__(16) __half g_Wv16[(size_t)HID_*CIN];   // PERMUTED rows
__device__ __align__(16) __half g_Wo16[(size_t)OUT_*HID_];  // unpermuted
__device__ float g_Wb_p[HID_];
__device__ float g_Wvb_p[HID_];
__device__ __align__(16) __half g_Pk [(size_t)B_*NH*L_*HD];    // [b,h][i][d]
__device__ __align__(16) __half g_Pq [(size_t)B_*NH*L_*HD];    // [b,h][k][d] (pre-scaled log2e/sqrt(128))
__device__ __align__(16) __half g_PvT[(size_t)B_*NH*HD*L_];    // [b,h][j][i]
__device__ __align__(16) __half g_attn[(size_t)B_*NH*L_*L_];   // attnT: [b,h][k][i]
__device__ __align__(16) __half g_OTh[(size_t)B_*HID_*L_];     // O^T fp16: [b][j*8+h][k]

// ---------------- helpers ----------------
__device__ __forceinline__ uint32_t cvta_s(const void* p){
    return (uint32_t)__cvta_generic_to_shared(p);
}
__device__ __forceinline__ void ldm_x4(uint32_t* r, uint32_t a){
    asm volatile("ldmatrix.sync.aligned.m8n8.x4.shared.b16 {%0,%1,%2,%3},[%4];\n"
        :"=r"(r[0]),"=r"(r[1]),"=r"(r[2]),"=r"(r[3]):"r"(a));
}
__device__ __forceinline__ void ldm_x4t(uint32_t* r, uint32_t a){
    asm volatile("ldmatrix.sync.aligned.m8n8.x4.trans.shared.b16 {%0,%1,%2,%3},[%4];\n"
        :"=r"(r[0]),"=r"(r[1]),"=r"(r[2]),"=r"(r[3]):"r"(a));
}
__device__ __forceinline__ void mma_f16(float* d, const uint32_t* a, const uint32_t* b, const float* c){
    asm volatile("mma.sync.aligned.m16n8k16.row.col.f32.f16.f16.f32 "
        "{%0,%1,%2,%3},{%4,%5,%6,%7},{%8,%9},{%10,%11,%12,%13};\n"
        :"=f"(d[0]),"=f"(d[1]),"=f"(d[2]),"=f"(d[3])
        :"r"(a[0]),"r"(a[1]),"r"(a[2]),"r"(a[3]),"r"(b[0]),"r"(b[1]),
         "f"(c[0]),"f"(c[1]),"f"(c[2]),"f"(c[3]));
}
__device__ __forceinline__ void mma_f16h(uint32_t* d, const uint32_t* a, const uint32_t* b){
    asm volatile("mma.sync.aligned.m16n8k16.row.col.f16.f16.f16.f16 "
        "{%0,%1},{%2,%3,%4,%5},{%6,%7},{%8,%9};\n"
        :"=r"(d[0]),"=r"(d[1])
        :"r"(a[0]),"r"(a[1]),"r"(a[2]),"r"(a[3]),"r"(b[0]),"r"(b[1]),
         "r"(d[0]),"r"(d[1]));
}
__device__ __forceinline__ void cp16(void* dst_smem, const void* src){
    uint32_t d = cvta_s(dst_smem);
    asm volatile("cp.async.cg.shared.global [%0],[%1],16;\n"::"r"(d),"l"(src));
}
#define CP_COMMIT() asm volatile("cp.async.commit_group;\n")
#define CP_WAIT(n)  asm volatile("cp.async.wait_group %0;\n"::"n"(n))

// =============================================================================
// Kernel 0a: inputs fp32 -> fp16 (3 segments)
// =============================================================================
__global__ void cvt3_kernel(const float* __restrict__ s0,
                            const float* __restrict__ s1,
                            const float* __restrict__ s2, int n4)
{
    const float* s = (blockIdx.y==0)? s0 : (blockIdx.y==1)? s1 : s2;
    __half* d = (blockIdx.y==0)? g_K16 : (blockIdx.y==1)? g_V16 : g_Q16;
    int i = blockIdx.x * blockDim.x + threadIdx.x;
    if (i < n4){
        float4 v = *(const float4*)(s + (size_t)i*4);
        __half2* o = (__half2*)(d + (size_t)i*4);
        o[0] = __floats2half2_rn(v.x, v.y);
        o[1] = __floats2half2_rn(v.z, v.w);
    }
}

// =============================================================================
// Kernel 0b: weights fp32 -> fp16; W/Wv rows permuted p=(n&7)*128+(n>>3)
// =============================================================================
__global__ void cvtw_kernel(const float* __restrict__ Ww,
                            const float* __restrict__ Wv,
                            const float* __restrict__ Wo,
                            const float* __restrict__ wb,
                            const float* __restrict__ wvb)
{
    int i = blockIdx.x * blockDim.x + threadIdx.x;
    if (blockIdx.y < 2){
        const float* s = blockIdx.y ? Wv : Ww;
        __half* d = blockIdx.y ? g_Wv16 : g_Ww16;
        int row = i >> 6, c4 = i & 63;
        int pr = (row & 7)*128 + (row >> 3);
        float4 v = *(const float4*)(s + (size_t)i*4);
        __half2* o = (__half2*)(d + ((size_t)pr*CIN) + c4*4);
        o[0] = __floats2half2_rn(v.x, v.y);
        o[1] = __floats2half2_rn(v.z, v.w);
    } else {
        float4 v = *(const float4*)(Wo + (size_t)i*4);
        __half2* o = (__half2*)(g_Wo16 + (size_t)i*4);
        o[0] = __floats2half2_rn(v.x, v.y);
        o[1] = __floats2half2_rn(v.z, v.w);
        if (i < HID_){
            int p = (i & 7)*128 + (i >> 3);
            g_Wb_p[p]  = wb[i];
            g_Wvb_p[p] = wvb[i];
        }
    }
}

// =============================================================================
// Kernel 1a: K/Q projection, fp16 accumulators
// =============================================================================
#define PR_NS (CIN/32)   // 8
__global__ __launch_bounds__(256,2) void proj16_kernel()
{
    extern __shared__ __align__(16) __half p16_s[];
    __half (*Ah)[128][40] = (__half(*)[128][40])(p16_s);
    __half (*Bh)[128][40] = (__half(*)[128][40])(p16_s + 3*128*40);
    __half (*stage)[136]  = (__half(*)[136])(p16_s);

    const int which = blockIdx.z;                     // 0=K, 1=Q
    const __half* A16 = which ? g_Q16 : g_K16;
    const float*  bias= g_Wb_p;

    const int tid  = threadIdx.x;
    const int lane = tid & 31, wid = tid >> 5;
    const int wm = wid >> 1, wn = wid & 1;
    const int m0 = blockIdx.y * 128, n0 = blockIdx.x * 128;

    uint32_t acc[2][8][2];
    #pragma unroll
    for (int i=0;i<2;i++){ for(int j=0;j<8;j++){ acc[i][j][0]=0u; acc[i][j][1]=0u; } }

    const int lr = tid >> 2, lc = (tid & 3) * 8;

    #define P16_LOAD(ss) do {                                                \
        int _buf = (ss)%3; int _kk = (ss)*32;                                \
        _Pragma("unroll")                                                    \
        for (int _t=0; _t<2; _t++){                                          \
            int _r = lr + _t*64;                                             \
            cp16(&Ah[_buf][_r][lc], A16 + (size_t)(m0+_r)*CIN + _kk + lc);   \
            cp16(&Bh[_buf][_r][lc], g_Ww16 + (size_t)(n0+_r)*CIN + _kk + lc);\
        }                                                                    \
        CP_COMMIT();                                                         \
    } while(0)

    P16_LOAD(0); P16_LOAD(1);

    for (int s=0; s<PR_NS; s++){
        if (s < PR_NS-1) CP_WAIT(1); else CP_WAIT(0);
        __syncthreads();
        if (s+2 < PR_NS) P16_LOAD(s+2);
        const int cb = s%3;
        #pragma unroll
        for (int ks=0; ks<2; ks++){
            uint32_t af[2][4];
            #pragma unroll
            for (int mt=0; mt<2; mt++)
                ldm_x4(af[mt], cvta_s(&Ah[cb][wm*32+mt*16+(lane&15)][ks*16+(lane>>4)*8]));
            uint32_t bf[8][2];
            #pragma unroll
            for (int p=0;p<4;p++){
                uint32_t r4[4];
                ldm_x4(r4, cvta_s(&Bh[cb][wn*64+p*16+(lane&15)][ks*16+(lane>>4)*8]));
                bf[2*p][0]=r4[0]; bf[2*p][1]=r4[2]; bf[2*p+1][0]=r4[1]; bf[2*p+1][1]=r4[3];
            }
            #pragma unroll
            for (int mt=0; mt<2; mt++){
                #pragma unroll
                for (int nt=0; nt<8; nt++)
                    mma_f16h(acc[mt][nt], af[mt], bf[nt]);
            }
        }
    }
    #undef P16_LOAD

    __syncthreads();

    const float qs = which ? (0.08838834764831845f * 1.4426950408889634f) : 1.0f;
    const int hh = n0 >> 7;
    const int b  = m0 >> 11, l0 = m0 & 2047;

    #pragma unroll
    for (int mt=0; mt<2; mt++){
        #pragma unroll
        for (int nt=0; nt<8; nt++){
            #pragma unroll
            for (int p=0; p<2; p++){
                int l = wm*32 + mt*16 + (lane>>2) + p*8;
                int d = wn*64 + nt*8 + (lane&3)*2;
                float2 f = __half22float2(*(__half2*)&acc[mt][nt][p]);
                __half2 v = __floats2half2_rn(
                    (f.x + bias[n0+d])   * qs,
                    (f.y + bias[n0+d+1]) * qs);
                *(__half2*)&stage[l][d] = v;
            }
        }
    }
    __syncthreads();

    #pragma unroll
    for (int t=0; t<8; t++){
        int idx = tid + t*256;
        int r = idx >> 4, c = (idx & 15) * 8;
        uint4 v = *(uint4*)&stage[r][c];
        __half* P = which ? g_Pq : g_Pk;
        *(uint4*)&P[((size_t)(b*NH+hh)*L_ + l0 + r)*HD + c] = v;
    }
}

// =============================================================================
// Kernel 1b: V projection, fp32 accumulators, transposed epilogue
// =============================================================================
__global__ __launch_bounds__(256,2) void projv_kernel()
{
    extern __shared__ __align__(16) __half pv_s[];
    __half (*Ah)[128][40] = (__half(*)[128][40])(pv_s);
    __half (*Bh)[128][40] = (__half(*)[128][40])(pv_s + 3*128*40);
    __half (*stage)[136]  = (__half(*)[136])(pv_s);

    const int tid  = threadIdx.x;
    const int lane = tid & 31, wid = tid >> 5;
    const int wm = wid >> 1, wn = wid & 1;
    const int m0 = blockIdx.y * 128, n0 = blockIdx.x * 128;

    float acc[2][8][4];
    #pragma unroll
    for (int i=0;i<2;i++){ for(int j=0;j<8;j++){ for(int e=0;e<4;e++) acc[i][j][e]=0.f; } }

    const int lr = tid >> 2, lc = (tid & 3) * 8;

    #define PV_LOAD(ss) do {                                                 \
        int _buf = (ss)%3; int _kk = (ss)*32;                                \
        _Pragma("unroll")                                                    \
        for (int _t=0; _t<2; _t++){                                          \
            int _r = lr + _t*64;                                             \
            cp16(&Ah[_buf][_r][lc], g_V16 + (size_t)(m0+_r)*CIN + _kk + lc); \
            cp16(&Bh[_buf][_r][lc], g_Wv16 + (size_t)(n0+_r)*CIN + _kk + lc);\
        }                                                                    \
        CP_COMMIT();                                                         \
    } while(0)

    PV_LOAD(0); PV_LOAD(1);

    for (int s=0; s<PR_NS; s++){
        if (s < PR_NS-1) CP_WAIT(1); else CP_WAIT(0);
        __syncthreads();
        if (s+2 < PR_NS) PV_LOAD(s+2);
        const int cb = s%3;
        #pragma unroll
        for (int ks=0; ks<2; ks++){
            uint32_t af[2][4];
            #pragma unroll
            for (int mt=0; mt<2; mt++)
                ldm_x4(af[mt], cvta_s(&Ah[cb][wm*32+mt*16+(lane&15)][ks*16+(lane>>4)*8]));
            uint32_t bf[8][2];
            #pragma unroll
            for (int p=0;p<4;p++){
                uint32_t r4[4];
                ldm_x4(r4, cvta_s(&Bh[cb][wn*64+p*16+(lane&15)][ks*16+(lane>>4)*8]));
                bf[2*p][0]=r4[0]; bf[2*p][1]=r4[2]; bf[2*p+1][0]=r4[1]; bf[2*p+1][1]=r4[3];
            }
            #pragma unroll
            for (int mt=0; mt<2; mt++){
                #pragma unroll
                for (int nt=0; nt<8; nt++)
                    mma_f16(acc[mt][nt], af[mt], bf[nt], acc[mt][nt]);
            }
        }
    }
    #undef PV_LOAD

    __syncthreads();

    const int hh = n0 >> 7;
    const int b  = m0 >> 11, l0 = m0 & 2047;

    #pragma unroll
    for (int mt=0; mt<2; mt++){
        #pragma unroll
        for (int nt=0; nt<8; nt++){
            #pragma unroll
            for (int e=0; e<4; e++){
                int l = wm*32 + mt*16 + (lane>>2) + (e>>1)*8;
                int d = wn*64 + nt*8 + (lane&3)*2 + (e&1);
                stage[d][l] = __float2half_rn(acc[mt][nt][e] + g_Wvb_p[n0+d]);
            }
        }
    }
    __syncthreads();

    #pragma unroll
    for (int t=0; t<8; t++){
        int idx = tid + t*256;
        int r = idx >> 4, c = (idx & 15) * 8;
        uint4 v = *(uint4*)&stage[r][c];
        *(uint4*)&g_PvT[((size_t)(b*NH+hh)*HD + r)*L_ + l0 + c] = v;
    }
}

// =============================================================================
// Kernel 2: scores + softmax over heads -> attnT [k][i]
//   Tile 64(k) x 128(i). FIXED load coverage: Ks 128 rows x 16 cp16 (8 iters),
//   Qs 64 rows x 16 cp16 (4 iters).
// =============================================================================
__global__ __launch_bounds__(256,1) void score_softmax_kernel()
{
    extern __shared__ __align__(16) __half s_dyn[];
    __half (*Ks)[128][136] = (__half(*)[128][136])(s_dyn);              // i-rows, 3 bufs
    __half (*Qs)[64][136]  = (__half(*)[64][136])(s_dyn + 3*128*136);   // k-rows, 3 bufs
    __half (*attn_s)[64][136] = (__half(*)[64][136])(s_dyn);            // [8][64][136] post-MMA

    const int b  = blockIdx.z;
    const int i0 = blockIdx.y * 128, k0 = blockIdx.x * 64;
    const int tid = threadIdx.x, lane = tid & 31, wid = tid >> 5;
    const int wk = wid & 1, wi2 = wid >> 1;    // warp tile: 32(k) x 32(i); 2x4 grid

    uint32_t acc[NH][2][4][2];                 // [h][mt(k16)][nt(i8)][2]
    #pragma unroll
    for (int h=0;h<NH;h++){ for(int mt=0;mt<2;mt++){ for(int nt=0;nt<4;nt++){
        acc[h][mt][nt][0]=0u; acc[h][mt][nt][1]=0u; } } }

    #define SC_LOAD(hh) do {                                                  \
        int _buf = (hh)%3;                                                    \
        const __half* _Kp = g_Pk + (((size_t)(b*NH+(hh)))*L_ + i0)*HD;        \
        const __half* _Qp = g_Pq + (((size_t)(b*NH+(hh)))*L_ + k0)*HD;        \
        _Pragma("unroll")                                                     \
        for (int _it=0; _it<8; _it++){                                        \
            int _idx = tid + _it*256;                                         \
            int _r = _idx >> 4, _c = (_idx & 15) * 8;                         \
            cp16(&Ks[_buf][_r][_c], _Kp + (size_t)_r*HD + _c);                \
        }                                                                     \
        _Pragma("unroll")                                                     \
        for (int _it=0; _it<4; _it++){                                        \
            int _idx = tid + _it*256;                                         \
            int _r = _idx >> 4, _c = (_idx & 15) * 8;                         \
            cp16(&Qs[_buf][_r][_c], _Qp + (size_t)_r*HD + _c);                \
        }                                                                     \
        CP_COMMIT();                                                          \
    } while(0)

    SC_LOAD(0); SC_LOAD(1);

    #pragma unroll
    for (int h=0; h<NH; h++){
        if (h < NH-1) CP_WAIT(1); else CP_WAIT(0);
        __syncthreads();
        if (h+2 < NH) SC_LOAD(h+2);
        const int cb = h%3;
        #pragma unroll
        for (int ks=0; ks<8; ks++){
            uint32_t af[2][4];
            #pragma unroll
            for (int mt=0; mt<2; mt++)
                ldm_x4(af[mt], cvta_s(&Qs[cb][wk*32+mt*16+(lane&15)][ks*16+(lane>>4)*8]));
            uint32_t bf[4][2];
            #pragma unroll
            for (int p=0;p<2;p++){
                uint32_t r4[4];
                ldm_x4(r4, cvta_s(&Ks[cb][wi2*32+p*16+(lane&15)][ks*16+(lane>>4)*8]));
                bf[2*p][0]=r4[0]; bf[2*p][1]=r4[2]; bf[2*p+1][0]=r4[1]; bf[2*p+1][1]=r4[3];
            }
            #pragma unroll
            for (int mt=0; mt<2; mt++){
                #pragma unroll
                for (int nt=0; nt<4; nt++)
                    mma_f16h(acc[h][mt][nt], af[mt], bf[nt]);
            }
        }
        __syncthreads();
    }
    #undef SC_LOAD

    // softmax over heads (acc = score*log2e); stage to attn_s[h][k][i]
    #pragma unroll
    for (int mt=0; mt<2; mt++){
        #pragma unroll
        for (int nt=0; nt<4; nt++){
            #pragma unroll
            for (int p=0; p<2; p++){
                __half2 e[NH];
                e[0] = h2exp2(*(__half2*)&acc[0][mt][nt][p]);
                __half2 s = e[0];
                #pragma unroll
                for (int h=1;h<NH;h++){
                    e[h] = h2exp2(*(__half2*)&acc[h][mt][nt][p]);
                    s = __hadd2(s, e[h]);
                }
                float2 sf = __half22float2(s);
                __half2 r = __floats2half2_rn(__fdividef(1.f, sf.x), __fdividef(1.f, sf.y));
                int kl = wk*32 + mt*16 + (lane>>2) + p*8;
                int il = wi2*32 + nt*8 + (lane&3)*2;
                #pragma unroll
                for (int h=0;h<NH;h++)
                    *(__half2*)&attn_s[h][kl][il] = __hmul2(e[h], r);
            }
        }
    }
    __syncthreads();

    // coalesced copy-out: 8 x 64 rows of 256B
    #pragma unroll
    for (int t=0; t<32; t++){
        int idx = tid + t*256;            // 8192 uint4
        int row = idx >> 4, c = (idx & 15) * 8;
        int h = row >> 6,  k = row & 63;
        uint4 v = *(uint4*)&attn_s[h][k][c];
        *(uint4*)&g_attn[(((size_t)(b*NH+h))*L_ + k0 + k)*L_ + i0 + c] = v;
    }
}

// =============================================================================
// Kernel 3: O^T[j][k] = sum_i PvT[j][i] * attnT[k][i]  -> fp16 g_OTh
// =============================================================================
#define AV_NS (L_/64)
__global__ __launch_bounds__(256,2) void av_kernel()
{
    extern __shared__ __align__(16) __half s_dyn2[];
    __half (*As)[128][72] = (__half(*)[128][72])(s_dyn2);
    __half (*Bs)[128][72] = (__half(*)[128][72])(s_dyn2 + 3*128*72);

    const int b = blockIdx.z, h = blockIdx.y;
    const int k0 = blockIdx.x * 128;
    const int tid = threadIdx.x, lane = tid & 31, wid = tid >> 5;
    const int wj = wid >> 1, wk = wid & 1;

    float acc[2][8][4];
    #pragma unroll
    for (int i=0;i<2;i++){ for(int j=0;j<8;j++){ for(int e=0;e<4;e++) acc[i][j][e]=0.f; } }

    const __half* At = g_attn + ((size_t)(b*NH+h))*L_*L_ + (size_t)k0*L_;
    const __half* Vt = g_PvT  + ((size_t)(b*NH+h))*HD*L_;

    const int lr = tid >> 3;
    const int lc = (tid & 7) * 8;

    #define AV_LOAD(ss) do {                                                  \
        int _buf = (ss)%3; int _i0 = (ss)*64;                                 \
        _Pragma("unroll")                                                     \
        for (int _it=0; _it<4; _it++){                                        \
            int _r = lr + _it*32;                                             \
            cp16(&As[_buf][_r][lc], Vt + (size_t)_r*L_ + _i0 + lc);           \
            cp16(&Bs[_buf][_r][lc], At + (size_t)_r*L_ + _i0 + lc);           \
        }                                                                     \
        CP_COMMIT();                                                          \
    } while(0)

    AV_LOAD(0); AV_LOAD(1);

    for (int s=0; s<AV_NS; s++){
        if (s < AV_NS-1) CP_WAIT(1); else CP_WAIT(0);
        __syncthreads();
        if (s+2 < AV_NS) AV_LOAD(s+2);
        const int cb = s%3;
        #pragma unroll
        for (int ks=0; ks<4; ks++){
            uint32_t af[2][4];
            #pragma unroll
            for (int mt=0; mt<2; mt++)
                ldm_x4(af[mt], cvta_s(&As[cb][wj*32+mt*16+(lane&15)][ks*16+(lane>>4)*8]));
            uint32_t bf[8][2];
            #pragma unroll
            for (int p=0;p<4;p++){
                uint32_t r4[4];
                ldm_x4(r4, cvta_s(&Bs[cb][wk*64+p*16+(lane&15)][ks*16+(lane>>4)*8]));
                bf[2*p][0]=r4[0]; bf[2*p][1]=r4[2]; bf[2*p+1][0]=r4[1]; bf[2*p+1][1]=r4[3];
            }
            #pragma unroll
            for (int mt=0; mt<2; mt++){
                #pragma unroll
                for (int nt=0; nt<8; nt++)
                    mma_f16(acc[mt][nt], af[mt], bf[nt], acc[mt][nt]);
            }
        }
    }
    #undef AV_LOAD

    #pragma unroll
    for (int mt=0; mt<2; mt++){
        #pragma unroll
        for (int nt=0; nt<8; nt++){
            #pragma unroll
            for (int p=0; p<2; p++){
                int j = wj*32 + mt*16 + (lane>>2) + p*8;
                int k = k0 + wk*64 + nt*8 + (lane&3)*2;
                __half2 v = __floats2half2_rn(acc[mt][nt][p*2+0], acc[mt][nt][p*2+1]);
                *(__half2*)&g_OTh[((size_t)b*HID_ + j*NH + h)*L_ + k] = v;
            }
        }
    }
}

// =============================================================================
// Kernel 4: final GEMM  out[8192,256] = O @ Wo^T + bias
// =============================================================================
#define FN_NS (HID_/32)  // 32
__global__ __launch_bounds__(256,2) void final_kernel(
    const float* __restrict__ bias, float* __restrict__ Cout)
{
    extern __shared__ __align__(16) __half fn_s[];
    __half (*At)[32][72] = (__half(*)[32][72])(fn_s);
    __half (*Bh)[128][40] = (__half(*)[128][40])(fn_s + 3*32*72);

    const int tid  = threadIdx.x;
    const int lane = tid & 31, wid = tid >> 5;
    const int wm = wid >> 2, wn = wid & 3;
    const int m0 = blockIdx.y * 64, n0 = blockIdx.x * 128;
    const int b  = m0 >> 11, l0 = m0 & 2047;

    float acc[2][4][4];
    #pragma unroll
    for (int i=0;i<2;i++){ for(int j=0;j<4;j++){ for(int e=0;e<4;e++) acc[i][j][e]=0.f; } }

    const int ar = tid >> 3, ac = (tid & 7) * 8;
    const int br = tid >> 2, bc = (tid & 3) * 8;

    #define FN_LOAD(ss) do {                                                  \
        int _buf = (ss)%3; int _kk = (ss)*32;                                 \
        cp16(&At[_buf][ar][ac], g_OTh + ((size_t)b*HID_ + _kk + ar)*L_ + l0 + ac); \
        _Pragma("unroll")                                                     \
        for (int _t=0; _t<2; _t++){                                           \
            int _r = br + _t*64;                                              \
            cp16(&Bh[_buf][_r][bc], g_Wo16 + (size_t)(n0+_r)*HID_ + _kk + bc); \
        }                                                                     \
        CP_COMMIT();                                                          \
    } while(0)

    FN_LOAD(0); FN_LOAD(1);

    for (int s=0; s<FN_NS; s++){
        if (s < FN_NS-1) CP_WAIT(1); else CP_WAIT(0);
        __syncthreads();
        if (s+2 < FN_NS) FN_LOAD(s+2);
        const int cb = s%3;
        #pragma unroll
        for (int ks=0; ks<2; ks++){
            uint32_t af[2][4];
            #pragma unroll
            for (int mt=0; mt<2; mt++)
                ldm_x4t(af[mt], cvta_s(
                    &At[cb][ks*16 + (lane&7) + ((lane>>4)&1)*8][wm*32 + mt*16 + ((lane>>3)&1)*8]));
            uint32_t bf[4][2];
            #pragma unroll
            for (int p=0;p<2;p++){
                uint32_t r4[4];
                ldm_x4(r4, cvta_s(&Bh[cb][wn*32+p*16+(lane&15)][ks*16+(lane>>4)*8]));
                bf[2*p][0]=r4[0]; bf[2*p][1]=r4[2]; bf[2*p+1][0]=r4[1]; bf[2*p+1][1]=r4[3];
            }
            #pragma unroll
            for (int mt=0; mt<2; mt++){
                #pragma unroll
                for (int nt=0; nt<4; nt++)
                    mma_f16(acc[mt][nt], af[mt], bf[nt], acc[mt][nt]);
            }
        }
    }
    #undef FN_LOAD

    #pragma unroll
    for (int mt=0; mt<2; mt++){
        #pragma unroll
        for (int nt=0; nt<4; nt++){
            #pragma unroll
            for (int e=0; e<4; e++){
                int m = m0 + wm*32 + mt*16 + (lane>>2) + (e>>1)*8;
                int n = n0 + wn*32 + nt*8 + (lane&3)*2 + (e&1);
                Cout[(size_t)m*OUT_ + n] = acc[mt][nt][e] + bias[n];
            }
        }
    }
}

// =============================================================================
extern "C" void kernel_launch(void* const* d_in, const int* in_sizes, int n_in,
                              void* d_out, int out_size)
{
    const float* KEY   = (const float*)d_in[0];
    const float* VALUE = (const float*)d_in[1];
    const float* QUERY = (const float*)d_in[2];
    const float* W_w   = (const float*)d_in[3];
    const float* W_b   = (const float*)d_in[4];
    const float* Wv_w  = (const float*)d_in[5];
    const float* Wv_b  = (const float*)d_in[6];
    const float* Wo_w  = (const float*)d_in[7];
    const float* Wo_b  = (const float*)d_in[8];
    float* out = (float*)d_out;

    // side stream + events, created once (host-side infra; identical work
    // is enqueued on every call — no work caching / call-count behavior).
    static cudaStream_t s2 = nullptr;
    static cudaEvent_t evStart = nullptr, evW = nullptr, evC3 = nullptr, evS2 = nullptr;
    if (!s2){
        cudaStreamCreateWithFlags(&s2, cudaStreamNonBlocking);
        cudaEventCreateWithFlags(&evStart, cudaEventDisableTiming);
        cudaEventCreateWithFlags(&evW,     cudaEventDisableTiming);
        cudaEventCreateWithFlags(&evC3,    cudaEventDisableTiming);
        cudaEventCreateWithFlags(&evS2,    cudaEventDisableTiming);
    }

    const int DYN_PR = 6*128*40*2;                    // 61440
    const int DYN_SC = 3*(128*136 + 64*136)*2;        // 156672
    const int DYN_AV = 6*128*72*2;                    // 110592
    const int DYN_FN = 3*32*72*2 + 3*128*40*2;        // 44544
    cudaFuncSetAttribute(proj16_kernel,        cudaFuncAttributeMaxDynamicSharedMemorySize, DYN_PR);
    cudaFuncSetAttribute(projv_kernel,         cudaFuncAttributeMaxDynamicSharedMemorySize, DYN_PR);
    cudaFuncSetAttribute(score_softmax_kernel, cudaFuncAttributeMaxDynamicSharedMemorySize, DYN_SC);
    cudaFuncSetAttribute(av_kernel,            cudaFuncAttributeMaxDynamicSharedMemorySize, DYN_AV);
    cudaFuncSetAttribute(final_kernel,         cudaFuncAttributeMaxDynamicSharedMemorySize, DYN_FN);

    dim3 blk(256);
    // fork: side stream does cvtw -> projv, overlapping cvt3/proj16/score
    cudaEventRecord(evStart, 0);
    cudaStreamWaitEvent(s2, evStart, 0);
    cvtw_kernel<<<dim3(HID_*CIN/4/256, 3), blk, 0, s2>>>(W_w, Wv_w, Wo_w, W_b, Wv_b);
    cudaEventRecord(evW, s2);

    cvt3_kernel<<<dim3(MTOT*CIN/4/256, 3), blk>>>(KEY, VALUE, QUERY, MTOT*CIN/4);
    cudaEventRecord(evC3, 0);

    cudaStreamWaitEvent(s2, evC3, 0);
    projv_kernel<<<dim3(8,64), blk, DYN_PR, s2>>>();
    cudaEventRecord(evS2, s2);

    cudaStreamWaitEvent(0, evW, 0);
    proj16_kernel<<<dim3(8,64,2), blk, DYN_PR>>>();
    score_softmax_kernel<<<dim3(L_/64, L_/128, B_), blk, DYN_SC>>>();
    cudaStreamWaitEvent(0, evS2, 0);
    av_kernel<<<dim3(L_/128, NH, B_), blk, DYN_AV>>>();
    final_kernel<<<dim3(2,128), blk, DYN_FN>>>(Wo_b, out);
}

// round 12
// speedup vs baseline: 1.0354x; 1.0354x over previous
#include <cuda_runtime.h>
#include <cuda_fp16.h>
#include <stdint.h>

#define B_   4
#define L_   2048
#define CIN  256
#define HID_ 1024
#define NH   8
#define HD   128
#define OUT_ 256
#define MTOT (B_*L_)   // 8192

// ---------------- scratch (device globals; no allocs allowed) ----------------
__device__ __align__(16) __half g_K16[(size_t)MTOT*CIN];
__device__ __align__(16) __half g_V16[(size_t)MTOT*CIN];
__device__ __align__(16) __half g_Q16[(size_t)MTOT*CIN];
__device__ __align__(16) __half g_Ww16[(size_t)HID_*CIN];   // PERMUTED rows: p=(n&7)*128+(n>>3)
__device__ __align__(16) __half g_Wv16[(size_t)HID_*CIN];   // PERMUTED rows
__device__ __align__(16) __half g_Wo16[(size_t)OUT_*HID_];  // unpermuted
__device__ float g_Wb_p[HID_];
__device__ float g_Wvb_p[HID_];
__device__ __align__(16) __half g_Pk [(size_t)B_*NH*L_*HD];    // [b,h][i][d]
__device__ __align__(16) __half g_Pq [(size_t)B_*NH*L_*HD];    // [b,h][k][d] (pre-scaled log2e/sqrt(128))
__device__ __align__(16) __half g_PvT[(size_t)B_*NH*HD*L_];    // [b,h][j][i]
__device__ __align__(16) __half g_attn[(size_t)B_*NH*L_*L_];   // attnT: [b,h][k][i]
__device__ __align__(16) __half g_OTh[(size_t)B_*HID_*L_];     // O^T fp16: [b][j*8+h][k]

// ---------------- helpers ----------------
__device__ __forceinline__ uint32_t cvta_s(const void* p){
    return (uint32_t)__cvta_generic_to_shared(p);
}
__device__ __forceinline__ void ldm_x4(uint32_t* r, uint32_t a){
    asm volatile("ldmatrix.sync.aligned.m8n8.x4.shared.b16 {%0,%1,%2,%3},[%4];\n"
        :"=r"(r[0]),"=r"(r[1]),"=r"(r[2]),"=r"(r[3]):"r"(a));
}
__device__ __forceinline__ void ldm_x4t(uint32_t* r, uint32_t a){
    asm volatile("ldmatrix.sync.aligned.m8n8.x4.trans.shared.b16 {%0,%1,%2,%3},[%4];\n"
        :"=r"(r[0]),"=r"(r[1]),"=r"(r[2]),"=r"(r[3]):"r"(a));
}
__device__ __forceinline__ void mma_f16(float* d, const uint32_t* a, const uint32_t* b, const float* c){
    asm volatile("mma.sync.aligned.m16n8k16.row.col.f32.f16.f16.f32 "
        "{%0,%1,%2,%3},{%4,%5,%6,%7},{%8,%9},{%10,%11,%12,%13};\n"
        :"=f"(d[0]),"=f"(d[1]),"=f"(d[2]),"=f"(d[3])
        :"r"(a[0]),"r"(a[1]),"r"(a[2]),"r"(a[3]),"r"(b[0]),"r"(b[1]),
         "f"(c[0]),"f"(c[1]),"f"(c[2]),"f"(c[3]));
}
__device__ __forceinline__ void mma_f16h(uint32_t* d, const uint32_t* a, const uint32_t* b){
    asm volatile("mma.sync.aligned.m16n8k16.row.col.f16.f16.f16.f16 "
        "{%0,%1},{%2,%3,%4,%5},{%6,%7},{%8,%9};\n"
        :"=r"(d[0]),"=r"(d[1])
        :"r"(a[0]),"r"(a[1]),"r"(a[2]),"r"(a[3]),"r"(b[0]),"r"(b[1]),
         "r"(d[0]),"r"(d[1]));
}
__device__ __forceinline__ void cp16(void* dst_smem, const void* src){
    uint32_t d = cvta_s(dst_smem);
    asm volatile("cp.async.cg.shared.global [%0],[%1],16;\n"::"r"(d),"l"(src));
}
#define CP_COMMIT() asm volatile("cp.async.commit_group;\n")
#define CP_WAIT(n)  asm volatile("cp.async.wait_group %0;\n"::"n"(n))

// =============================================================================
// Kernel 0a: inputs fp32 -> fp16 (3 segments)
// =============================================================================
__global__ void cvt3_kernel(const float* __restrict__ s0,
                            const float* __restrict__ s1,
                            const float* __restrict__ s2, int n4)
{
    const float* s = (blockIdx.y==0)? s0 : (blockIdx.y==1)? s1 : s2;
    __half* d = (blockIdx.y==0)? g_K16 : (blockIdx.y==1)? g_V16 : g_Q16;
    int i = blockIdx.x * blockDim.x + threadIdx.x;
    if (i < n4){
        float4 v = *(const float4*)(s + (size_t)i*4);
        __half2* o = (__half2*)(d + (size_t)i*4);
        o[0] = __floats2half2_rn(v.x, v.y);
        o[1] = __floats2half2_rn(v.z, v.w);
    }
}

// =============================================================================
// Kernel 0b: weights fp32 -> fp16; W/Wv rows permuted p=(n&7)*128+(n>>3)
// =============================================================================
__global__ void cvtw_kernel(const float* __restrict__ Ww,
                            const float* __restrict__ Wv,
                            const float* __restrict__ Wo,
                            const float* __restrict__ wb,
                            const float* __restrict__ wvb)
{
    int i = blockIdx.x * blockDim.x + threadIdx.x;
    if (blockIdx.y < 2){
        const float* s = blockIdx.y ? Wv : Ww;
        __half* d = blockIdx.y ? g_Wv16 : g_Ww16;
        int row = i >> 6, c4 = i & 63;
        int pr = (row & 7)*128 + (row >> 3);
        float4 v = *(const float4*)(s + (size_t)i*4);
        __half2* o = (__half2*)(d + ((size_t)pr*CIN) + c4*4);
        o[0] = __floats2half2_rn(v.x, v.y);
        o[1] = __floats2half2_rn(v.z, v.w);
    } else {
        float4 v = *(const float4*)(Wo + (size_t)i*4);
        __half2* o = (__half2*)(g_Wo16 + (size_t)i*4);
        o[0] = __floats2half2_rn(v.x, v.y);
        o[1] = __floats2half2_rn(v.z, v.w);
        if (i < HID_){
            int p = (i & 7)*128 + (i >> 3);
            g_Wb_p[p]  = wb[i];
            g_Wvb_p[p] = wvb[i];
        }
    }
}

// =============================================================================
// Kernel 1a: K/Q projection, fp16 accumulators
// =============================================================================
#define PR_NS (CIN/32)   // 8
__global__ __launch_bounds__(256,2) void proj16_kernel()
{
    extern __shared__ __align__(16) __half p16_s[];
    __half (*Ah)[128][40] = (__half(*)[128][40])(p16_s);
    __half (*Bh)[128][40] = (__half(*)[128][40])(p16_s + 3*128*40);
    __half (*stage)[136]  = (__half(*)[136])(p16_s);

    const int which = blockIdx.z;                     // 0=K, 1=Q
    const __half* A16 = which ? g_Q16 : g_K16;
    const float*  bias= g_Wb_p;

    const int tid  = threadIdx.x;
    const int lane = tid & 31, wid = tid >> 5;
    const int wm = wid >> 1, wn = wid & 1;
    const int m0 = blockIdx.y * 128, n0 = blockIdx.x * 128;

    uint32_t acc[2][8][2];
    #pragma unroll
    for (int i=0;i<2;i++){ for(int j=0;j<8;j++){ acc[i][j][0]=0u; acc[i][j][1]=0u; } }

    const int lr = tid >> 2, lc = (tid & 3) * 8;

    #define P16_LOAD(ss) do {                                                \
        int _buf = (ss)%3; int _kk = (ss)*32;                                \
        _Pragma("unroll")                                                    \
        for (int _t=0; _t<2; _t++){                                          \
            int _r = lr + _t*64;                                             \
            cp16(&Ah[_buf][_r][lc], A16 + (size_t)(m0+_r)*CIN + _kk + lc);   \
            cp16(&Bh[_buf][_r][lc], g_Ww16 + (size_t)(n0+_r)*CIN + _kk + lc);\
        }                                                                    \
        CP_COMMIT();                                                         \
    } while(0)

    P16_LOAD(0); P16_LOAD(1);

    for (int s=0; s<PR_NS; s++){
        if (s < PR_NS-1) CP_WAIT(1); else CP_WAIT(0);
        __syncthreads();
        if (s+2 < PR_NS) P16_LOAD(s+2);
        const int cb = s%3;
        #pragma unroll
        for (int ks=0; ks<2; ks++){
            uint32_t af[2][4];
            #pragma unroll
            for (int mt=0; mt<2; mt++)
                ldm_x4(af[mt], cvta_s(&Ah[cb][wm*32+mt*16+(lane&15)][ks*16+(lane>>4)*8]));
            uint32_t bf[8][2];
            #pragma unroll
            for (int p=0;p<4;p++){
                uint32_t r4[4];
                ldm_x4(r4, cvta_s(&Bh[cb][wn*64+p*16+(lane&15)][ks*16+(lane>>4)*8]));
                bf[2*p][0]=r4[0]; bf[2*p][1]=r4[2]; bf[2*p+1][0]=r4[1]; bf[2*p+1][1]=r4[3];
            }
            #pragma unroll
            for (int mt=0; mt<2; mt++){
                #pragma unroll
                for (int nt=0; nt<8; nt++)
                    mma_f16h(acc[mt][nt], af[mt], bf[nt]);
            }
        }
    }
    #undef P16_LOAD

    __syncthreads();

    const float qs = which ? (0.08838834764831845f * 1.4426950408889634f) : 1.0f;
    const int hh = n0 >> 7;
    const int b  = m0 >> 11, l0 = m0 & 2047;

    #pragma unroll
    for (int mt=0; mt<2; mt++){
        #pragma unroll
        for (int nt=0; nt<8; nt++){
            #pragma unroll
            for (int p=0; p<2; p++){
                int l = wm*32 + mt*16 + (lane>>2) + p*8;
                int d = wn*64 + nt*8 + (lane&3)*2;
                float2 f = __half22float2(*(__half2*)&acc[mt][nt][p]);
                __half2 v = __floats2half2_rn(
                    (f.x + bias[n0+d])   * qs,
                    (f.y + bias[n0+d+1]) * qs);
                *(__half2*)&stage[l][d] = v;
            }
        }
    }
    __syncthreads();

    #pragma unroll
    for (int t=0; t<8; t++){
        int idx = tid + t*256;
        int r = idx >> 4, c = (idx & 15) * 8;
        uint4 v = *(uint4*)&stage[r][c];
        __half* P = which ? g_Pq : g_Pk;
        *(uint4*)&P[((size_t)(b*NH+hh)*L_ + l0 + r)*HD + c] = v;
    }
}

// =============================================================================
// Kernel 1b: V projection, fp32 accumulators, transposed epilogue
// =============================================================================
__global__ __launch_bounds__(256,2) void projv_kernel()
{
    extern __shared__ __align__(16) __half pv_s[];
    __half (*Ah)[128][40] = (__half(*)[128][40])(pv_s);
    __half (*Bh)[128][40] = (__half(*)[128][40])(pv_s + 3*128*40);
    __half (*stage)[136]  = (__half(*)[136])(pv_s);

    const int tid  = threadIdx.x;
    const int lane = tid & 31, wid = tid >> 5;
    const int wm = wid >> 1, wn = wid & 1;
    const int m0 = blockIdx.y * 128, n0 = blockIdx.x * 128;

    float acc[2][8][4];
    #pragma unroll
    for (int i=0;i<2;i++){ for(int j=0;j<8;j++){ for(int e=0;e<4;e++) acc[i][j][e]=0.f; } }

    const int lr = tid >> 2, lc = (tid & 3) * 8;

    #define PV_LOAD(ss) do {                                                 \
        int _buf = (ss)%3; int _kk = (ss)*32;                                \
        _Pragma("unroll")                                                    \
        for (int _t=0; _t<2; _t++){                                          \
            int _r = lr + _t*64;                                             \
            cp16(&Ah[_buf][_r][lc], g_V16 + (size_t)(m0+_r)*CIN + _kk + lc); \
            cp16(&Bh[_buf][_r][lc], g_Wv16 + (size_t)(n0+_r)*CIN + _kk + lc);\
        }                                                                    \
        CP_COMMIT();                                                         \
    } while(0)

    PV_LOAD(0); PV_LOAD(1);

    for (int s=0; s<PR_NS; s++){
        if (s < PR_NS-1) CP_WAIT(1); else CP_WAIT(0);
        __syncthreads();
        if (s+2 < PR_NS) PV_LOAD(s+2);
        const int cb = s%3;
        #pragma unroll
        for (int ks=0; ks<2; ks++){
            uint32_t af[2][4];
            #pragma unroll
            for (int mt=0; mt<2; mt++)
                ldm_x4(af[mt], cvta_s(&Ah[cb][wm*32+mt*16+(lane&15)][ks*16+(lane>>4)*8]));
            uint32_t bf[8][2];
            #pragma unroll
            for (int p=0;p<4;p++){
                uint32_t r4[4];
                ldm_x4(r4, cvta_s(&Bh[cb][wn*64+p*16+(lane&15)][ks*16+(lane>>4)*8]));
                bf[2*p][0]=r4[0]; bf[2*p][1]=r4[2]; bf[2*p+1][0]=r4[1]; bf[2*p+1][1]=r4[3];
            }
            #pragma unroll
            for (int mt=0; mt<2; mt++){
                #pragma unroll
                for (int nt=0; nt<8; nt++)
                    mma_f16(acc[mt][nt], af[mt], bf[nt], acc[mt][nt]);
            }
        }
    }
    #undef PV_LOAD

    __syncthreads();

    const int hh = n0 >> 7;
    const int b  = m0 >> 11, l0 = m0 & 2047;

    #pragma unroll
    for (int mt=0; mt<2; mt++){
        #pragma unroll
        for (int nt=0; nt<8; nt++){
            #pragma unroll
            for (int e=0; e<4; e++){
                int l = wm*32 + mt*16 + (lane>>2) + (e>>1)*8;
                int d = wn*64 + nt*8 + (lane&3)*2 + (e&1);
                stage[d][l] = __float2half_rn(acc[mt][nt][e] + g_Wvb_p[n0+d]);
            }
        }
    }
    __syncthreads();

    #pragma unroll
    for (int t=0; t<8; t++){
        int idx = tid + t*256;
        int r = idx >> 4, c = (idx & 15) * 8;
        uint4 v = *(uint4*)&stage[r][c];
        *(uint4*)&g_PvT[((size_t)(b*NH+hh)*HD + r)*L_ + l0 + c] = v;
    }
}

// =============================================================================
// Kernel 2: scores (fp16 acc) + packed-fp16 softmax over heads -> attnT [k][i]
//   R9-proven 64x64 tile, 2 CTAs/SM.
// =============================================================================
__global__ __launch_bounds__(256,2) void score_softmax_kernel()
{
    extern __shared__ __align__(16) __half s_dyn[];
    __half (*Ks)[64][136] = (__half(*)[64][136])(s_dyn);
    __half (*Qs)[64][136] = (__half(*)[64][136])(s_dyn + 3*64*136);
    __half (*attn_s)[64][72] = (__half(*)[64][72])(s_dyn);

    const int b  = blockIdx.z;
    const int i0 = blockIdx.y * 64, k0 = blockIdx.x * 64;
    const int tid = threadIdx.x, lane = tid & 31, wid = tid >> 5;
    const int wi = wid >> 1, wk = wid & 1;

    uint32_t acc[NH][4][2];
    #pragma unroll
    for (int h=0;h<NH;h++){ for(int nt=0;nt<4;nt++){ acc[h][nt][0]=0u; acc[h][nt][1]=0u; } }

    const int lr = tid >> 4, lc = (tid & 15) * 8;

    #define SC_LOAD(hh) do {                                                  \
        int _buf = (hh)%3;                                                    \
        const __half* _Kp = g_Pk + (((size_t)(b*NH+(hh)))*L_ + i0)*HD;        \
        const __half* _Qp = g_Pq + (((size_t)(b*NH+(hh)))*L_ + k0)*HD;        \
        _Pragma("unroll")                                                     \
        for (int _it=0; _it<4; _it++){                                        \
            int _r = lr + _it*16;                                             \
            cp16(&Ks[_buf][_r][lc], _Kp + (size_t)_r*HD + lc);                \
            cp16(&Qs[_buf][_r][lc], _Qp + (size_t)_r*HD + lc);                \
        }                                                                     \
        CP_COMMIT();                                                          \
    } while(0)

    SC_LOAD(0); SC_LOAD(1);

    #pragma unroll
    for (int h=0; h<NH; h++){
        if (h < NH-1) CP_WAIT(1); else CP_WAIT(0);
        __syncthreads();
        if (h+2 < NH) SC_LOAD(h+2);
        const int cb = h%3;
        #pragma unroll
        for (int ks=0; ks<8; ks++){
            uint32_t af[4];
            ldm_x4(af, cvta_s(&Qs[cb][wi*16+(lane&15)][ks*16+(lane>>4)*8]));
            uint32_t bf[4][2];
            #pragma unroll
            for (int p=0;p<2;p++){
                uint32_t r4[4];
                ldm_x4(r4, cvta_s(&Ks[cb][wk*32+p*16+(lane&15)][ks*16+(lane>>4)*8]));
                bf[2*p][0]=r4[0]; bf[2*p][1]=r4[2]; bf[2*p+1][0]=r4[1]; bf[2*p+1][1]=r4[3];
            }
            #pragma unroll
            for (int nt=0; nt<4; nt++) mma_f16h(acc[h][nt], af, bf[nt]);
        }
    }
    #undef SC_LOAD

    __syncthreads();

    #pragma unroll
    for (int nt=0; nt<4; nt++){
        #pragma unroll
        for (int p=0; p<2; p++){
            __half2 e[NH];
            e[0] = h2exp2(*(__half2*)&acc[0][nt][p]);
            __half2 s = e[0];
            #pragma unroll
            for (int h=1;h<NH;h++){
                e[h] = h2exp2(*(__half2*)&acc[h][nt][p]);
                s = __hadd2(s, e[h]);
            }
            float2 sf = __half22float2(s);
            __half2 r = __floats2half2_rn(__fdividef(1.f, sf.x), __fdividef(1.f, sf.y));
            int kl = wi*16 + (lane>>2) + p*8;
            int il = wk*32 + nt*8 + (lane&3)*2;
            #pragma unroll
            for (int h=0;h<NH;h++)
                *(__half2*)&attn_s[h][kl][il] = __hmul2(e[h], r);
        }
    }
    __syncthreads();

    #pragma unroll
    for (int t=0; t<16; t++){
        int idx = tid + t*256;
        int row = idx >> 3, c = (idx & 7) * 8;
        int h = row >> 6,  k = row & 63;
        uint4 v = *(uint4*)&attn_s[h][k][c];
        *(uint4*)&g_attn[(((size_t)(b*NH+h))*L_ + k0 + k)*L_ + i0 + c] = v;
    }
}

// =============================================================================
// Kernel 3: O^T[j][k] = sum_i PvT[j][i] * attnT[k][i]  -> fp16 g_OTh
// =============================================================================
#define AV_NS (L_/64)
__global__ __launch_bounds__(256,2) void av_kernel()
{
    extern __shared__ __align__(16) __half s_dyn2[];
    __half (*As)[128][72] = (__half(*)[128][72])(s_dyn2);
    __half (*Bs)[128][72] = (__half(*)[128][72])(s_dyn2 + 3*128*72);

    const int b = blockIdx.z, h = blockIdx.y;
    const int k0 = blockIdx.x * 128;
    const int tid = threadIdx.x, lane = tid & 31, wid = tid >> 5;
    const int wj = wid >> 1, wk = wid & 1;

    float acc[2][8][4];
    #pragma unroll
    for (int i=0;i<2;i++){ for(int j=0;j<8;j++){ for(int e=0;e<4;e++) acc[i][j][e]=0.f; } }

    const __half* At = g_attn + ((size_t)(b*NH+h))*L_*L_ + (size_t)k0*L_;
    const __half* Vt = g_PvT  + ((size_t)(b*NH+h))*HD*L_;

    const int lr = tid >> 3;
    const int lc = (tid & 7) * 8;

    #define AV_LOAD(ss) do {                                                  \
        int _buf = (ss)%3; int _i0 = (ss)*64;                                 \
        _Pragma("unroll")                                                     \
        for (int _it=0; _it<4; _it++){                                        \
            int _r = lr + _it*32;                                             \
            cp16(&As[_buf][_r][lc], Vt + (size_t)_r*L_ + _i0 + lc);           \
            cp16(&Bs[_buf][_r][lc], At + (size_t)_r*L_ + _i0 + lc);           \
        }                                                                     \
        CP_COMMIT();                                                          \
    } while(0)

    AV_LOAD(0); AV_LOAD(1);

    for (int s=0; s<AV_NS; s++){
        if (s < AV_NS-1) CP_WAIT(1); else CP_WAIT(0);
        __syncthreads();
        if (s+2 < AV_NS) AV_LOAD(s+2);
        const int cb = s%3;
        #pragma unroll
        for (int ks=0; ks<4; ks++){
            uint32_t af[2][4];
            #pragma unroll
            for (int mt=0; mt<2; mt++)
                ldm_x4(af[mt], cvta_s(&As[cb][wj*32+mt*16+(lane&15)][ks*16+(lane>>4)*8]));
            uint32_t bf[8][2];
            #pragma unroll
            for (int p=0;p<4;p++){
                uint32_t r4[4];
                ldm_x4(r4, cvta_s(&Bs[cb][wk*64+p*16+(lane&15)][ks*16+(lane>>4)*8]));
                bf[2*p][0]=r4[0]; bf[2*p][1]=r4[2]; bf[2*p+1][0]=r4[1]; bf[2*p+1][1]=r4[3];
            }
            #pragma unroll
            for (int mt=0; mt<2; mt++){
                #pragma unroll
                for (int nt=0; nt<8; nt++)
                    mma_f16(acc[mt][nt], af[mt], bf[nt], acc[mt][nt]);
            }
        }
    }
    #undef AV_LOAD

    #pragma unroll
    for (int mt=0; mt<2; mt++){
        #pragma unroll
        for (int nt=0; nt<8; nt++){
            #pragma unroll
            for (int p=0; p<2; p++){
                int j = wj*32 + mt*16 + (lane>>2) + p*8;
                int k = k0 + wk*64 + nt*8 + (lane&3)*2;
                __half2 v = __floats2half2_rn(acc[mt][nt][p*2+0], acc[mt][nt][p*2+1]);
                *(__half2*)&g_OTh[((size_t)b*HID_ + j*NH + h)*L_ + k] = v;
            }
        }
    }
}

// =============================================================================
// Kernel 4: final GEMM  out[8192,256] = O @ Wo^T + bias
// =============================================================================
#define FN_NS (HID_/32)  // 32
__global__ __launch_bounds__(256,2) void final_kernel(
    const float* __restrict__ bias, float* __restrict__ Cout)
{
    extern __shared__ __align__(16) __half fn_s[];
    __half (*At)[32][72] = (__half(*)[32][72])(fn_s);
    __half (*Bh)[128][40] = (__half(*)[128][40])(fn_s + 3*32*72);

    const int tid  = threadIdx.x;
    const int lane = tid & 31, wid = tid >> 5;
    const int wm = wid >> 2, wn = wid & 3;
    const int m0 = blockIdx.y * 64, n0 = blockIdx.x * 128;
    const int b  = m0 >> 11, l0 = m0 & 2047;

    float acc[2][4][4];
    #pragma unroll
    for (int i=0;i<2;i++){ for(int j=0;j<4;j++){ for(int e=0;e<4;e++) acc[i][j][e]=0.f; } }

    const int ar = tid >> 3, ac = (tid & 7) * 8;
    const int br = tid >> 2, bc = (tid & 3) * 8;

    #define FN_LOAD(ss) do {                                                  \
        int _buf = (ss)%3; int _kk = (ss)*32;                                 \
        cp16(&At[_buf][ar][ac], g_OTh + ((size_t)b*HID_ + _kk + ar)*L_ + l0 + ac); \
        _Pragma("unroll")                                                     \
        for (int _t=0; _t<2; _t++){                                           \
            int _r = br + _t*64;                                              \
            cp16(&Bh[_buf][_r][bc], g_Wo16 + (size_t)(n0+_r)*HID_ + _kk + bc); \
        }                                                                     \
        CP_COMMIT();                                                          \
    } while(0)

    FN_LOAD(0); FN_LOAD(1);

    for (int s=0; s<FN_NS; s++){
        if (s < FN_NS-1) CP_WAIT(1); else CP_WAIT(0);
        __syncthreads();
        if (s+2 < FN_NS) FN_LOAD(s+2);
        const int cb = s%3;
        #pragma unroll
        for (int ks=0; ks<2; ks++){
            uint32_t af[2][4];
            #pragma unroll
            for (int mt=0; mt<2; mt++)
                ldm_x4t(af[mt], cvta_s(
                    &At[cb][ks*16 + (lane&7) + ((lane>>4)&1)*8][wm*32 + mt*16 + ((lane>>3)&1)*8]));
            uint32_t bf[4][2];
            #pragma unroll
            for (int p=0;p<2;p++){
                uint32_t r4[4];
                ldm_x4(r4, cvta_s(&Bh[cb][wn*32+p*16+(lane&15)][ks*16+(lane>>4)*8]));
                bf[2*p][0]=r4[0]; bf[2*p][1]=r4[2]; bf[2*p+1][0]=r4[1]; bf[2*p+1][1]=r4[3];
            }
            #pragma unroll
            for (int mt=0; mt<2; mt++){
                #pragma unroll
                for (int nt=0; nt<4; nt++)
                    mma_f16(acc[mt][nt], af[mt], bf[nt], acc[mt][nt]);
            }
        }
    }
    #undef FN_LOAD

    #pragma unroll
    for (int mt=0; mt<2; mt++){
        #pragma unroll
        for (int nt=0; nt<4; nt++){
            #pragma unroll
            for (int e=0; e<4; e++){
                int m = m0 + wm*32 + mt*16 + (lane>>2) + (e>>1)*8;
                int n = n0 + wn*32 + nt*8 + (lane&3)*2 + (e&1);
                Cout[(size_t)m*OUT_ + n] = acc[mt][nt][e] + bias[n];
            }
        }
    }
}

// =============================================================================
extern "C" void kernel_launch(void* const* d_in, const int* in_sizes, int n_in,
                              void* d_out, int out_size)
{
    const float* KEY   = (const float*)d_in[0];
    const float* VALUE = (const float*)d_in[1];
    const float* QUERY = (const float*)d_in[2];
    const float* W_w   = (const float*)d_in[3];
    const float* W_b   = (const float*)d_in[4];
    const float* Wv_w  = (const float*)d_in[5];
    const float* Wv_b  = (const float*)d_in[6];
    const float* Wo_w  = (const float*)d_in[7];
    const float* Wo_b  = (const float*)d_in[8];
    float* out = (float*)d_out;

    // side stream + events, created once (host-side infra; identical work
    // is enqueued on every call).
    static cudaStream_t s2 = nullptr;
    static cudaEvent_t evStart = nullptr, evW = nullptr, evC3 = nullptr, evS2 = nullptr;
    if (!s2){
        cudaStreamCreateWithFlags(&s2, cudaStreamNonBlocking);
        cudaEventCreateWithFlags(&evStart, cudaEventDisableTiming);
        cudaEventCreateWithFlags(&evW,     cudaEventDisableTiming);
        cudaEventCreateWithFlags(&evC3,    cudaEventDisableTiming);
        cudaEventCreateWithFlags(&evS2,    cudaEventDisableTiming);
    }

    const int DYN_PR = 6*128*40*2;                   // 61440
    const int DYN_SC = 6*64*136*2;                   // 104448
    const int DYN_AV = 6*128*72*2;                   // 110592
    const int DYN_FN = 3*32*72*2 + 3*128*40*2;       // 44544
    cudaFuncSetAttribute(proj16_kernel,        cudaFuncAttributeMaxDynamicSharedMemorySize, DYN_PR);
    cudaFuncSetAttribute(projv_kernel,         cudaFuncAttributeMaxDynamicSharedMemorySize, DYN_PR);
    cudaFuncSetAttribute(score_softmax_kernel, cudaFuncAttributeMaxDynamicSharedMemorySize, DYN_SC);
    cudaFuncSetAttribute(av_kernel,            cudaFuncAttributeMaxDynamicSharedMemorySize, DYN_AV);
    cudaFuncSetAttribute(final_kernel,         cudaFuncAttributeMaxDynamicSharedMemorySize, DYN_FN);

    dim3 blk(256);
    // fork: side stream does cvtw -> projv, overlapping cvt3/proj16/score
    cudaEventRecord(evStart, 0);
    cudaStreamWaitEvent(s2, evStart, 0);
    cvtw_kernel<<<dim3(HID_*CIN/4/256, 3), blk, 0, s2>>>(W_w, Wv_w, Wo_w, W_b, Wv_b);
    cudaEventRecord(evW, s2);

    cvt3_kernel<<<dim3(MTOT*CIN/4/256, 3), blk>>>(KEY, VALUE, QUERY, MTOT*CIN/4);
    cudaEventRecord(evC3, 0);

    cudaStreamWaitEvent(s2, evC3, 0);
    projv_kernel<<<dim3(8,64), blk, DYN_PR, s2>>>();
    cudaEventRecord(evS2, s2);

    cudaStreamWaitEvent(0, evW, 0);
    proj16_kernel<<<dim3(8,64,2), blk, DYN_PR>>>();
    score_softmax_kernel<<<dim3(L_/64, L_/64, B_), blk, DYN_SC>>>();
    cudaStreamWaitEvent(0, evS2, 0);
    av_kernel<<<dim3(L_/128, NH, B_), blk, DYN_AV>>>();
    final_kernel<<<dim3(2,128), blk, DYN_FN>>>(Wo_b, out);
}